// round 7
// baseline (speedup 1.0000x reference)
#include <cuda_runtime.h>

#define FFT_N  4096
#define NT     256
#define PAD(i) ((i) + (((i) >> 4) << 1))          // pad stride 18 (float4-friendly)
#define SMEM_E (FFT_N + ((FFT_N >> 4) << 1))      // 4608 float2 = 36864 B

__device__ __forceinline__ float2 cadd(float2 a, float2 b) { return make_float2(a.x + b.x, a.y + b.y); }
__device__ __forceinline__ float2 csub(float2 a, float2 b) { return make_float2(a.x - b.x, a.y - b.y); }
__device__ __forceinline__ float2 cmul(float2 a, float2 b) {
    return make_float2(fmaf(a.x, b.x, -a.y * b.y), fmaf(a.x, b.y, a.y * b.x));
}
template <int DIR>
__device__ __forceinline__ float2 rotI(float2 z) {
    return (DIR < 0) ? make_float2(z.y, -z.x) : make_float2(-z.y, z.x);
}
template <int DIR>
__device__ __forceinline__ float2 cmulc(float2 z, float cr, float ci_fwd) {
    float ci = (DIR < 0) ? ci_fwd : -ci_fwd;
    return cmul(z, make_float2(cr, ci));
}

template <int DIR>
__device__ __forceinline__ void dft4(float2& a, float2& b, float2& c, float2& d) {
    float2 t0 = cadd(a, c), t1 = csub(a, c);
    float2 t2 = cadd(b, d), t3 = rotI<DIR>(csub(b, d));
    a = cadd(t0, t2);
    b = cadd(t1, t3);
    c = csub(t0, t2);
    d = csub(t1, t3);
}

// 16-point DFT as 4x4; input natural, X[k1+4*k2] at v[4*k1+k2] -> OUT() for stores.
#define OUT(q) ((((q) & 3) << 2) | ((q) >> 2))

template <int DIR>
__device__ __forceinline__ void dft16(float2 v[16]) {
    const float C1 = 0.92387953251128675613f;
    const float S1 = 0.38268343236508977173f;
    const float H  = 0.70710678118654752440f;
    dft4<DIR>(v[0], v[4], v[8],  v[12]);
    dft4<DIR>(v[1], v[5], v[9],  v[13]);
    dft4<DIR>(v[2], v[6], v[10], v[14]);
    dft4<DIR>(v[3], v[7], v[11], v[15]);
    v[5]  = cmulc<DIR>(v[5],  C1, -S1);
    v[6]  = cmulc<DIR>(v[6],  H,  -H );
    v[7]  = cmulc<DIR>(v[7],  S1, -C1);
    v[9]  = cmulc<DIR>(v[9],  H,  -H );
    v[10] = rotI<DIR>(v[10]);
    v[11] = cmulc<DIR>(v[11], -H, -H );
    v[13] = cmulc<DIR>(v[13], S1, -C1);
    v[14] = cmulc<DIR>(v[14], -H, -H );
    v[15] = cmulc<DIR>(v[15], -C1, S1);
    dft4<DIR>(v[0],  v[1],  v[2],  v[3]);
    dft4<DIR>(v[4],  v[5],  v[6],  v[7]);
    dft4<DIR>(v[8],  v[9],  v[10], v[11]);
    dft4<DIR>(v[12], v[13], v[14], v[15]);
}

// v[r] *= exp(i*theta*r), r=1..15; two 8-step chains anchored by MUFU sincos.
__device__ __forceinline__ void twiddle_ladder(float2 v[16], float theta) {
    float s1, c1, s8, c8;
    __sincosf(theta, &s1, &c1);
    __sincosf(8.0f * theta, &s8, &c8);
    float ar = c1, ai = s1;            // chain A: r = 1..7
    float br = c8, bi = s8;            // chain B: r = 8..15
    v[8] = cmul(v[8], make_float2(br, bi));
#pragma unroll
    for (int r = 1; r < 8; r++) {
        v[r] = cmul(v[r], make_float2(ar, ai));
        float nbr = fmaf(br, c1, -(bi * s1));
        bi = fmaf(br, s1, bi * c1);
        br = nbr;
        v[8 + r] = cmul(v[8 + r], make_float2(br, bi));
        if (r < 7) {
            float nar = fmaf(ar, c1, -(ai * s1));
            ai = fmaf(ar, s1, ai * c1);
            ar = nar;
        }
    }
}

// Contiguous block write of v[OUT(q)] to sm[PAD(16*i+q)], q=0..15, as 8x STS.128.
__device__ __forceinline__ void store_block16(float2* sm, int i, const float2 v[16]) {
    float2* b = &sm[PAD(16 * i)];   // PAD(16i+q) = PAD(16i)+q for q<16; 16B-aligned
#pragma unroll
    for (int q = 0; q < 16; q += 2) {
        float2 e0 = v[OUT(q)], e1 = v[OUT(q + 1)];
        *reinterpret_cast<float4*>(b + q) = make_float4(e0.x, e0.y, e1.x, e1.y);
    }
}

// Middle Stockham radix-16 stage (S=16), in-place smem.
template <int DIR>
__device__ __forceinline__ void mid_stage(float2* sm, int i) {
    float2 v[16];
#pragma unroll
    for (int r = 0; r < 16; r++) v[r] = sm[PAD(i + NT * r)];
    int k = i & 15;
    float theta = ((DIR < 0) ? -6.283185307179586f : 6.283185307179586f)
                  * (float)k / 256.0f;
    twiddle_ladder(v, theta);
    dft16<DIR>(v);
    __syncthreads();
    int j = ((i & ~15) << 4) + k;
#pragma unroll
    for (int q = 0; q < 16; q++) sm[PAD(j + q * 16)] = v[OUT(q)];
    __syncthreads();
}

extern __shared__ float2 sm[];

__global__ void __launch_bounds__(NT, 4)
afdf16v_kernel(const float2* __restrict__ x, const float2* __restrict__ A,
               const float2* __restrict__ D, float2* __restrict__ out) {
    const int i = threadIdx.x;
    const size_t base = (size_t)blockIdx.x * FFT_N;

    // ---- fwd stage 0 (S=1, twiddle-free) fused with gmem load + A scale ----
    {
        float2 v[16];
#pragma unroll
        for (int r = 0; r < 16; r++) {
            int c = i + NT * r;
            float2 xv = x[base + c];
            float2 a = A[c];
            v[r] = make_float2(a.x * xv.x, a.y * xv.y);
        }
        dft16<-1>(v);
        store_block16(sm, i, v);
    }
    __syncthreads();

    // ---- fwd stage 1 (S=16) ----
    mid_stage<-1>(sm, i);

    // ---- fwd stage 2 (S=256) + D-scale + inv stage 0, in registers ----
    {
        float2 u[16];
#pragma unroll
        for (int r = 0; r < 16; r++) u[r] = sm[PAD(i + NT * r)];
        twiddle_ladder(u, -6.283185307179586f * (float)i / (float)FFT_N);
        dft16<-1>(u);
        // u[OUT(q)] = F[i + 256*q]
        const float invN = 1.0f / (float)FFT_N;
        float2 g[16];
#pragma unroll
        for (int r = 0; r < 16; r++) {
            float2 fv = u[OUT(r)];
            float2 d = D[i + NT * r];
            g[r] = make_float2(d.x * fv.x * invN, d.y * fv.y * invN);
        }
        dft16<1>(g);   // inverse stage 0 over the stride-256 set we hold
        __syncthreads();
        store_block16(sm, i, g);
    }
    __syncthreads();

    // ---- inv stage 1 (S=16) ----
    mid_stage<1>(sm, i);

    // ---- inv stage 2 (S=256) -> gmem, coalesced ----
    {
        float2 u[16];
#pragma unroll
        for (int r = 0; r < 16; r++) u[r] = sm[PAD(i + NT * r)];
        twiddle_ladder(u, 6.283185307179586f * (float)i / (float)FFT_N);
        dft16<1>(u);
#pragma unroll
        for (int q = 0; q < 16; q++) out[base + i + NT * q] = u[OUT(q)];
    }
}

extern "C" void kernel_launch(void* const* d_in, const int* in_sizes, int n_in,
                              void* d_out, int out_size) {
    const float2* x = (const float2*)d_in[0];
    const float2* A = (const float2*)d_in[1];
    const float2* D = (const float2*)d_in[2];
    float2* out = (float2*)d_out;

    int rows = in_sizes[0] / (FFT_N * 2);   // (B, C, 2) float32 -> B rows

    const int smem_bytes = SMEM_E * sizeof(float2);  // 36864 B
    cudaFuncSetAttribute(afdf16v_kernel, cudaFuncAttributeMaxDynamicSharedMemorySize, smem_bytes);
    afdf16v_kernel<<<rows, NT, smem_bytes>>>(x, A, D, out);
}

// round 9
// speedup vs baseline: 1.8384x; 1.8384x over previous
#include <cuda_runtime.h>

#define FFT_N  4096
#define NT     256
#define PAD(i) ((i) + (((i) >> 4) << 1))          // pad stride 18 (float4-friendly)
#define SMEM_E (FFT_N + ((FFT_N >> 4) << 1))      // 4608 float2 = 36864 B

__device__ __forceinline__ float2 cadd(float2 a, float2 b) { return make_float2(a.x + b.x, a.y + b.y); }
__device__ __forceinline__ float2 csub(float2 a, float2 b) { return make_float2(a.x - b.x, a.y - b.y); }
__device__ __forceinline__ float2 cmul(float2 a, float2 b) {
    return make_float2(fmaf(a.x, b.x, -a.y * b.y), fmaf(a.x, b.y, a.y * b.x));
}
template <int DIR>
__device__ __forceinline__ float2 rotI(float2 z) {
    return (DIR < 0) ? make_float2(z.y, -z.x) : make_float2(-z.y, z.x);
}
template <int DIR>
__device__ __forceinline__ float2 cmulc(float2 z, float cr, float ci_fwd) {
    float ci = (DIR < 0) ? ci_fwd : -ci_fwd;
    return cmul(z, make_float2(cr, ci));
}

template <int DIR>
__device__ __forceinline__ void dft4(float2& a, float2& b, float2& c, float2& d) {
    float2 t0 = cadd(a, c), t1 = csub(a, c);
    float2 t2 = cadd(b, d), t3 = rotI<DIR>(csub(b, d));
    a = cadd(t0, t2);
    b = cadd(t1, t3);
    c = csub(t0, t2);
    d = csub(t1, t3);
}

// 16-point DFT as 4x4; input natural, X[k1+4*k2] at v[4*k1+k2] -> OUT() for stores.
#define OUT(q) ((((q) & 3) << 2) | ((q) >> 2))

template <int DIR>
__device__ __forceinline__ void dft16(float2 v[16]) {
    const float C1 = 0.92387953251128675613f;
    const float S1 = 0.38268343236508977173f;
    const float H  = 0.70710678118654752440f;
    dft4<DIR>(v[0], v[4], v[8],  v[12]);
    dft4<DIR>(v[1], v[5], v[9],  v[13]);
    dft4<DIR>(v[2], v[6], v[10], v[14]);
    dft4<DIR>(v[3], v[7], v[11], v[15]);
    v[5]  = cmulc<DIR>(v[5],  C1, -S1);
    v[6]  = cmulc<DIR>(v[6],  H,  -H );
    v[7]  = cmulc<DIR>(v[7],  S1, -C1);
    v[9]  = cmulc<DIR>(v[9],  H,  -H );
    v[10] = rotI<DIR>(v[10]);
    v[11] = cmulc<DIR>(v[11], -H, -H );
    v[13] = cmulc<DIR>(v[13], S1, -C1);
    v[14] = cmulc<DIR>(v[14], -H, -H );
    v[15] = cmulc<DIR>(v[15], -C1, S1);
    dft4<DIR>(v[0],  v[1],  v[2],  v[3]);
    dft4<DIR>(v[4],  v[5],  v[6],  v[7]);
    dft4<DIR>(v[8],  v[9],  v[10], v[11]);
    dft4<DIR>(v[12], v[13], v[14], v[15]);
}

// v[r] *= exp(i*theta*r), r=1..15; two 8-step chains anchored by MUFU sincos.
__device__ __forceinline__ void twiddle_ladder(float2 v[16], float theta) {
    float s1, c1, s8, c8;
    __sincosf(theta, &s1, &c1);
    __sincosf(8.0f * theta, &s8, &c8);
    float ar = c1, ai = s1;            // chain A: r = 1..7
    float br = c8, bi = s8;            // chain B: r = 8..15
    v[8] = cmul(v[8], make_float2(br, bi));
#pragma unroll
    for (int r = 1; r < 8; r++) {
        v[r] = cmul(v[r], make_float2(ar, ai));
        float nbr = fmaf(br, c1, -(bi * s1));
        bi = fmaf(br, s1, bi * c1);
        br = nbr;
        v[8 + r] = cmul(v[8 + r], make_float2(br, bi));
        if (r < 7) {
            float nar = fmaf(ar, c1, -(ai * s1));
            ai = fmaf(ar, s1, ai * c1);
            ar = nar;
        }
    }
}

// Contiguous block write of v[OUT(q)] to sm[PAD(16*i+q)], q=0..15, as 8x STS.128.
__device__ __forceinline__ void store_block16(float2* sm, int i, const float2 v[16]) {
    float2* b = &sm[PAD(16 * i)];   // PAD(16i+q) = PAD(16i)+q for q<16; 16B-aligned
#pragma unroll
    for (int q = 0; q < 16; q += 2) {
        float2 e0 = v[OUT(q)], e1 = v[OUT(q + 1)];
        *reinterpret_cast<float4*>(b + q) = make_float4(e0.x, e0.y, e1.x, e1.y);
    }
}

// Middle Stockham radix-16 stage (S=16), in-place smem.
template <int DIR>
__device__ __forceinline__ void mid_stage(float2* sm, int i) {
    float2 v[16];
#pragma unroll
    for (int r = 0; r < 16; r++) v[r] = sm[PAD(i + NT * r)];
    int k = i & 15;
    float theta = ((DIR < 0) ? -6.283185307179586f : 6.283185307179586f)
                  * (float)k / 256.0f;
    twiddle_ladder(v, theta);
    dft16<DIR>(v);
    __syncthreads();
    int j = ((i & ~15) << 4) + k;
#pragma unroll
    for (int q = 0; q < 16; q++) sm[PAD(j + q * 16)] = v[OUT(q)];
    __syncthreads();
}

extern __shared__ float2 sm[];

__global__ void __launch_bounds__(NT, 3)
afdf16s_kernel(const float2* __restrict__ x, const float2* __restrict__ A,
               const float2* __restrict__ D, float2* __restrict__ out) {
    const int i = threadIdx.x;
    const size_t base = (size_t)blockIdx.x * FFT_N;

    // ---- fwd stage 0 (S=1, twiddle-free) fused with gmem load + A scale ----
    {
        float2 v[16];
#pragma unroll
        for (int r = 0; r < 16; r++) {
            int c = i + NT * r;
            float2 xv = x[base + c];
            float2 a = A[c];
            v[r] = make_float2(a.x * xv.x, a.y * xv.y);
        }
        dft16<-1>(v);
        store_block16(sm, i, v);
    }
    __syncthreads();

    // ---- fwd stage 1 (S=16) ----
    mid_stage<-1>(sm, i);

    // ---- fwd stage 2 (S=256) + D-scale + inv stage 0, in registers ----
    {
        float2 u[16];
#pragma unroll
        for (int r = 0; r < 16; r++) u[r] = sm[PAD(i + NT * r)];
        twiddle_ladder(u, -6.283185307179586f * (float)i / (float)FFT_N);
        dft16<-1>(u);
        // u[OUT(q)] = F[i + 256*q]
        const float invN = 1.0f / (float)FFT_N;
        float2 g[16];
#pragma unroll
        for (int r = 0; r < 16; r++) {
            float2 fv = u[OUT(r)];
            float2 d = D[i + NT * r];
            g[r] = make_float2(d.x * fv.x * invN, d.y * fv.y * invN);
        }
        dft16<1>(g);   // inverse stage 0 over the stride-256 set we hold
        __syncthreads();
        store_block16(sm, i, g);
    }
    __syncthreads();

    // ---- inv stage 1 (S=16) ----
    mid_stage<1>(sm, i);

    // ---- inv stage 2 (S=256) -> gmem, coalesced ----
    {
        float2 u[16];
#pragma unroll
        for (int r = 0; r < 16; r++) u[r] = sm[PAD(i + NT * r)];
        twiddle_ladder(u, 6.283185307179586f * (float)i / (float)FFT_N);
        dft16<1>(u);
#pragma unroll
        for (int q = 0; q < 16; q++) out[base + i + NT * q] = u[OUT(q)];
    }
}

extern "C" void kernel_launch(void* const* d_in, const int* in_sizes, int n_in,
                              void* d_out, int out_size) {
    const float2* x = (const float2*)d_in[0];
    const float2* A = (const float2*)d_in[1];
    const float2* D = (const float2*)d_in[2];
    float2* out = (float2*)d_out;

    int rows = in_sizes[0] / (FFT_N * 2);   // (B, C, 2) float32 -> B rows

    const int smem_bytes = SMEM_E * sizeof(float2);  // 36864 B
    cudaFuncSetAttribute(afdf16s_kernel, cudaFuncAttributeMaxDynamicSharedMemorySize, smem_bytes);
    afdf16s_kernel<<<rows, NT, smem_bytes>>>(x, A, D, out);
}